// round 2
// baseline (speedup 1.0000x reference)
#include <cuda_runtime.h>
#include <cstdint>

#define HH 256
#define WW 256
#define NUM_CURVES 256
#define GPER 64                            /* 2 beziers * 32 samples */
#define NGAUSS (NUM_CURVES*GPER)           /* 16384 */
#define LOG2E 1.4426950408889634f
#define BATCH 1024
#define SUB 4

// ---- static scratch ----
__device__ float4   d_gA[NGAUSS];     // mx, my, c0p, c1p
__device__ float4   d_gB[NGAUSS];     // c2p, log2(alpha), cr, cg
__device__ float    d_gCb[NGAUSS];    // cb
__device__ uint32_t d_gTile[NGAUSS];  // packed uchar4: xlo,xhi,ylo,yhi (tile idx)

// ---------------------------------------------------------------------------
// K1 (fused prep + bezier): 64 blocks x 256 threads. Block b handles curves
// 4b..4b+3 (each curve -> 64 gaussians). Stable depth rank computed in
// parallel per block from a shared depth table.
// ---------------------------------------------------------------------------
__global__ void __launch_bounds__(256)
k_build(const float* __restrict__ ctrl,
        const float* __restrict__ fdc,
        const float* __restrict__ chol,
        const float* __restrict__ opac,
        const float* __restrict__ depth)
{
    __shared__ float  sd[NUM_CURVES];
    __shared__ int    srank[4];
    __shared__ float4 sConic[4];   // c0p, c1p, c2p, log2(alpha)
    __shared__ float4 sColEx[4];   // cr, cg, cb, ex
    __shared__ float  sEy[4];

    int t   = threadIdx.x;
    int grp = t >> 6;              // which of the block's 4 curves
    int li  = t & 63;              // lane within the curve group
    int ci  = blockIdx.x * 4 + grp;

    sd[t] = depth[t];
    if (t < 4) srank[t] = 0;
    __syncthreads();

    // --- stable rank of curve ci: 64 threads x 4 comparisons, warp-reduce ---
    {
        float d = sd[ci];
        int partial = 0;
        #pragma unroll
        for (int jj = 0; jj < 4; ++jj) {
            int j = li * 4 + jj;
            float dj = sd[j];
            partial += (dj < d) || (dj == d && j < ci);
        }
        partial += __shfl_xor_sync(0xffffffffu, partial, 16);
        partial += __shfl_xor_sync(0xffffffffu, partial, 8);
        partial += __shfl_xor_sync(0xffffffffu, partial, 4);
        partial += __shfl_xor_sync(0xffffffffu, partial, 2);
        partial += __shfl_xor_sync(0xffffffffu, partial, 1);
        if ((t & 31) == 0) atomicAdd(&srank[grp], partial);
    }

    // --- per-curve conic / color / extent (4 threads) ---
    if (t < 4) {
        int c = blockIdx.x * 4 + t;
        float c0 = chol[3*c+0] + 0.5f;
        float c1 = chol[3*c+1];
        float c2 = chol[3*c+2] + 0.5f;
        float s00 = c0*c0;
        float s01 = c0*c1;
        float s11 = c1*c1 + c2*c2;
        float inv = 1.0f / (s00*s11 - s01*s01);
        float A =  s11*inv;
        float B = -s01*inv;
        float C =  s00*inv;

        float al  = 1.0f / (1.0f + expf(-opac[c]));
        float l2a = log2f(al);

        // footprint: al*exp(-q/2) >= ~3.4e-9 -> q <= 2*(19.5 + ln al)
        float Q = fmaxf(2.0f * (19.5f + logf(al)), 0.0f);
        float ex = sqrtf(Q * s00);
        float ey = sqrtf(Q * s11);

        sConic[t] = make_float4(-0.5f*LOG2E*A, -LOG2E*B, -0.5f*LOG2E*C, l2a);
        sColEx[t] = make_float4(1.0f/(1.0f+expf(-fdc[3*c+0])),
                                1.0f/(1.0f+expf(-fdc[3*c+1])),
                                1.0f/(1.0f+expf(-fdc[3*c+2])), ex);
        sEy[t] = ey;
    }
    __syncthreads();

    // --- bezier point for this thread's gaussian ---
    int k = li >> 5;               // segment
    int s = li & 31;               // sample

    float tt = 0.007f + (float)s * (0.986f / 31.0f);
    float u  = 1.0f - tt;
    float t2 = tt*tt, t3 = t2*tt, t4 = t2*t2, t5 = t4*tt;
    float u2 = u*u,   u3 = u2*u,  u4 = u2*u2, u5 = u4*u;
    float w0 = u5;
    float w1 = 5.0f  * tt * u4;
    float w2 = 10.0f * t2 * u3;
    float w3 = 10.0f * t3 * u2;
    float w4 = 5.0f  * t4 * u;
    float w5 = t5;

    const float* cb_ = ctrl + ci * 20;
    int i0 = k*5;
    float px, py;
    {
        int a0=i0, a1=i0+1, a2=i0+2, a3=i0+3, a4=i0+4, a5=(i0+5)%10;
        px = w0*cb_[a0*2]   + w1*cb_[a1*2]   + w2*cb_[a2*2]
           + w3*cb_[a3*2]   + w4*cb_[a4*2]   + w5*cb_[a5*2];
        py = w0*cb_[a0*2+1] + w1*cb_[a1*2+1] + w2*cb_[a2*2+1]
           + w3*cb_[a3*2+1] + w4*cb_[a4*2+1] + w5*cb_[a5*2+1];
    }
    float mx = (tanhf(px)*0.5f + 0.5f) * (float)WW;
    float my = (tanhf(py)*0.5f + 0.5f) * (float)HH;

    float4 cc = sConic[grp];
    float4 ce = sColEx[grp];
    float  ey = sEy[grp];
    int slot  = srank[grp] * 64 + li;

    d_gA[slot]  = make_float4(mx, my, cc.x, cc.y);
    d_gB[slot]  = make_float4(cc.z, cc.w, ce.x, ce.y);
    d_gCb[slot] = ce.z;

    // tile bbox: tile hits iff |mx - (16tx+8)| <= ex+8  (16x16 tiles)
    float exl = ce.w;
    int xlo = max(0,  (int)ceilf ((mx - exl - 16.0f) * 0.0625f - 1e-4f));
    int xhi = min(15, (int)floorf((mx + exl)         * 0.0625f + 1e-4f));
    int ylo = max(0,  (int)ceilf ((my - ey  - 16.0f) * 0.0625f - 1e-4f));
    int yhi = min(15, (int)floorf((my + ey)          * 0.0625f + 1e-4f));
    uint32_t packed;
    if (xlo > xhi || ylo > yhi) packed = 0x000000FFu;   // xlo=255 -> never hits
    else packed = (uint32_t)xlo | ((uint32_t)xhi << 8) |
                  ((uint32_t)ylo << 16) | ((uint32_t)yhi << 24);
    d_gTile[slot] = packed;
}

// ---------------------------------------------------------------------------
// K2: tiled compositing. 256 blocks (16x16 px tiles), 256 threads.
// ---------------------------------------------------------------------------
__global__ void __launch_bounds__(256)
k_render(const float* __restrict__ bgp, float* __restrict__ out)
{
    __shared__ float4 shA[BATCH];
    __shared__ float4 shB[BATCH];
    __shared__ float  shCb[BATCH];
    __shared__ int    warpTot[SUB][8];

    int t    = threadIdx.x;
    int wid  = t >> 5;
    int lane = t & 31;
    int tileX = blockIdx.x & 15;
    int tileY = blockIdx.x >> 4;
    int pc = t & 15, pr = t >> 4;
    float px = (float)(tileX*16 + pc) + 0.5f;
    float py = (float)(tileY*16 + pr) + 0.5f;

    float T = 1.0f, cr = 0.0f, cg = 0.0f, cb = 0.0f;

    for (int base = 0; base < NGAUSS; base += BATCH) {
        if (__syncthreads_and(T < 1e-4f)) break;

        // --- cull SUB*256 gaussians via packed tile bbox, order-preserving ---
        unsigned bal[SUB];
        int flag[SUB];
        #pragma unroll
        for (int j = 0; j < SUB; ++j) {
            uint32_t tb = d_gTile[base + j*256 + t];
            int xlo =  tb        & 255;
            int xhi = (tb >> 8)  & 255;
            int ylo = (tb >> 16) & 255;
            int yhi =  tb >> 24;
            bool hit = (tileX >= xlo) & (tileX <= xhi) &
                       (tileY >= ylo) & (tileY <= yhi);
            flag[j] = hit;
            unsigned bb = __ballot_sync(0xffffffffu, hit);
            bal[j] = bb;
            if (lane == 0) warpTot[j][wid] = __popc(bb);
        }
        __syncthreads();

        int subBase[SUB];
        int running = 0;
        #pragma unroll
        for (int j = 0; j < SUB; ++j) {
            subBase[j] = running;
            #pragma unroll
            for (int w = 0; w < 8; ++w) running += warpTot[j][w];
        }
        int total = running;

        #pragma unroll
        for (int j = 0; j < SUB; ++j) {
            if (flag[j]) {
                int off = subBase[j] + __popc(bal[j] & ((1u << lane) - 1u));
                #pragma unroll
                for (int w = 0; w < 8; ++w)
                    if (w < wid) off += warpTot[j][w];
                int gidx = base + j*256 + t;
                shA[off]  = d_gA[gidx];
                shB[off]  = d_gB[gidx];
                shCb[off] = d_gCb[gidx];
            }
        }
        __syncthreads();

        // --- composite front-to-back, saturation check every 256 survivors ---
        for (int i0 = 0; i0 < total; i0 += 256) {
            int iend = min(i0 + 256, total);
            if (T >= 1e-4f) {
                for (int i = i0; i < iend; ++i) {
                    float4 A = shA[i];
                    float4 B = shB[i];
                    float dx = px - A.x;
                    float dy = py - A.y;
                    float e = B.y;                    // log2(alpha)
                    e = fmaf(A.z, dx*dx, e);
                    e = fmaf(A.w, dx*dy, e);
                    e = fmaf(B.x, dy*dy, e);
                    float a;
                    asm("ex2.approx.f32 %0, %1;" : "=f"(a) : "f"(e));
                    a = fminf(a, 0.999f);
                    float w = a * T;                  // off critical path
                    cr = fmaf(w, B.z, cr);
                    cg = fmaf(w, B.w, cg);
                    cb = fmaf(w, shCb[i], cb);
                    T  = fmaf(-a, T, T);              // 4-cycle chain
                }
            }
            if (iend < total && __syncthreads_and(T < 1e-4f)) break;
        }
    }

    float b0 = bgp[0], b1 = bgp[1], b2 = bgp[2];
    cr = fminf(fmaxf(fmaf(T, b0, cr), 0.0f), 1.0f);
    cg = fminf(fmaxf(fmaf(T, b1, cg), 0.0f), 1.0f);
    cb = fminf(fmaxf(fmaf(T, b2, cb), 0.0f), 1.0f);

    int o = ((tileY*16 + pr)*WW + (tileX*16 + pc)) * 3;
    out[o+0] = cr;
    out[o+1] = cg;
    out[o+2] = cb;
}

// ---------------------------------------------------------------------------
extern "C" void kernel_launch(void* const* d_in, const int* in_sizes, int n_in,
                              void* d_out, int out_size)
{
    const float* ctrl  = (const float*)d_in[0];  // (256,10,2)
    const float* fdc   = (const float*)d_in[1];  // (256,3)
    const float* chol  = (const float*)d_in[2];  // (256,3)
    const float* opac  = (const float*)d_in[3];  // (256,1)
    const float* depth = (const float*)d_in[4];  // (256,1)
    const float* bg    = (const float*)d_in[5];  // (3,)
    float* out = (float*)d_out;                  // (256,256,3)

    k_build<<<64, 256>>>(ctrl, fdc, chol, opac, depth);
    k_render<<<256, 256>>>(bg, out);
}